// round 6
// baseline (speedup 1.0000x reference)
#include <cuda_runtime.h>
#include <cuda_bf16.h>
#include <cstdint>

// SigLipLoss: loss = (1/N) * sum_ij softplus(s_ij), sign-flip on diagonal.
// Round 5: persistent CTAs, 256x128 tiles, bf16 mma.sync.
// Barrier-based pipeline (no mbarrier polling) + cross-barrier software
// pipelining of ldmatrix fragments so the LDS burst hides under MMA issue.

#define NN 8192
#define DD 768
#define BM 256
#define BN 128
#define BK 32
#define NTILES (NN / BM * NN / BN)    // 2048
#define KITERS (DD / BK)              // 24
#define NCTA 148
#define ROWBYTES (DD * 2)             // 1536

#define A_B   (BM * 64)               // 16384
#define STAGE_B ((BM + BN) * 64)      // 24576
#define STAGES 4
#define SMEM_TOTAL (STAGES * STAGE_B + 256)

__device__ __align__(16) __nv_bfloat16 g_Abf[NN * DD];
__device__ __align__(16) __nv_bfloat16 g_Bbf[NN * DD];
__device__ float g_partials[NTILES];
__device__ unsigned g_done;

__device__ __forceinline__ uint32_t smem_u32(const void* p) {
    uint32_t r;
    asm("{ .reg .u64 t; cvta.to.shared.u64 t, %1; cvt.u32.u64 %0, t; }"
        : "=r"(r) : "l"(p));
    return r;
}
__device__ __forceinline__ void cpa16(uint32_t dst, const void* src) {
    asm volatile("cp.async.cg.shared.global [%0], [%1], 16;"
                 :: "r"(dst), "l"(__cvta_generic_to_global(src)) : "memory");
}
__device__ __forceinline__ void ldm_x4(uint32_t* r, uint32_t addr) {
    asm volatile("ldmatrix.sync.aligned.m8n8.x4.shared.b16 {%0,%1,%2,%3}, [%4];"
                 : "=r"(r[0]), "=r"(r[1]), "=r"(r[2]), "=r"(r[3]) : "r"(addr));
}
__device__ __forceinline__ void mma16816(float* c, const uint32_t* a,
                                         const uint32_t* b) {
    asm volatile(
        "mma.sync.aligned.m16n8k16.row.col.f32.bf16.bf16.f32 "
        "{%0,%1,%2,%3}, {%4,%5,%6,%7}, {%8,%9}, {%0,%1,%2,%3};"
        : "+f"(c[0]), "+f"(c[1]), "+f"(c[2]), "+f"(c[3])
        : "r"(a[0]), "r"(a[1]), "r"(a[2]), "r"(a[3]), "r"(b[0]), "r"(b[1]));
}

__global__ void convert_kernel(const float* __restrict__ A,
                               const float* __restrict__ B) {
    if (blockIdx.x == 0 && threadIdx.x == 0) g_done = 0;
    const int total4 = NN * DD / 4;
    const int stride = gridDim.x * blockDim.x;
    __nv_bfloat162* pa = (__nv_bfloat162*)g_Abf;
    __nv_bfloat162* pb = (__nv_bfloat162*)g_Bbf;
    for (int i = blockIdx.x * blockDim.x + threadIdx.x; i < total4; i += stride) {
        float4 a = ((const float4*)A)[i];
        float4 b = ((const float4*)B)[i];
        pa[2 * i + 0] = __floats2bfloat162_rn(a.x, a.y);
        pa[2 * i + 1] = __floats2bfloat162_rn(a.z, a.w);
        pb[2 * i + 0] = __floats2bfloat162_rn(b.x, b.y);
        pb[2 * i + 1] = __floats2bfloat162_rn(b.z, b.w);
    }
}

__global__ __launch_bounds__(512, 1) void siglip_mma_kernel(float* __restrict__ out) {
    extern __shared__ char smem_raw[];
    __shared__ unsigned s_last;
    uint32_t sbase = smem_u32(smem_raw);
    sbase = (sbase + 127u) & ~127u;

    const int tid  = threadIdx.x;
    const int wid  = tid >> 5;
    const int lane = tid & 31;
    const int warp_m = wid & 7;
    const int warp_n = wid >> 3;
    const int cta = blockIdx.x;

    const int ntiles = (NTILES - cta + NCTA - 1) / NCTA;
    const int C = ntiles * KITERS;

    // ---- producer mapping: 3x 16B per thread per chunk ----
    const int r0 = tid >> 2;
    const int c4 = tid & 3;
    const uint32_t swz = (uint32_t)((c4 ^ ((r0 >> 1) & 3)) * 16);
    const uint32_t dstA0 = r0 * 64 + swz;
    const uint32_t dstA1 = dstA0 + 128 * 64;
    const uint32_t dstB0 = A_B + r0 * 64 + swz;
    const uint32_t cB16 = c4 * 16;

    int pKB = 0, pG = cta, issued = 0;
    const char* bA0 = (const char*)g_Abf
        + ((size_t)(pG >> 6) * BM + r0) * ROWBYTES + cB16;
    const char* bA1 = bA0 + (size_t)128 * ROWBYTES;
    const char* bB0 = (const char*)g_Bbf
        + ((size_t)(pG & 63) * BN + r0) * ROWBYTES + cB16;

#define ISSUE() do {                                                     \
        const uint32_t stb = sbase + (uint32_t)(issued & 3) * STAGE_B;   \
        cpa16(stb + dstA0, bA0 + pKB);                                   \
        cpa16(stb + dstA1, bA1 + pKB);                                   \
        cpa16(stb + dstB0, bB0 + pKB);                                   \
        asm volatile("cp.async.commit_group;" ::: "memory");             \
        ++issued;                                                        \
        pKB += 64;                                                       \
        if (pKB == DD * 2) {                                             \
            pKB = 0; pG += NCTA;                                         \
            if (pG < NTILES) {                                           \
                bA0 = (const char*)g_Abf                                 \
                    + ((size_t)(pG >> 6) * BM + r0) * ROWBYTES + cB16;   \
                bA1 = bA0 + (size_t)128 * ROWBYTES;                      \
                bB0 = (const char*)g_Bbf                                 \
                    + ((size_t)(pG & 63) * BN + r0) * ROWBYTES + cB16;   \
            }                                                            \
        }                                                                \
    } while (0)

    // ---- ldmatrix per-lane addresses (XOR swizzle) ----
    const int rowA = warp_m * 32 + (lane & 15);
    const uint32_t xa = (uint32_t)(((lane & 15) >> 1) & 3);
    const uint32_t ca = (uint32_t)(lane >> 4);
    const uint32_t aBase = rowA * 64;
    const uint32_t swzA0 = ((0 + ca) ^ xa) * 16;   // kk = 0
    const uint32_t swzA1 = ((2 + ca) ^ xa) * 16;   // kk = 1

    const int rowB = warp_n * 64 + (lane & 7) + ((lane >> 4) & 1) * 8;
    const uint32_t xb = (uint32_t)((rowB >> 1) & 3);
    const uint32_t cb = (uint32_t)((lane >> 3) & 1);
    const uint32_t bBase = A_B + rowB * 64;
    const uint32_t swzB0 = ((0 + cb) ^ xb) * 16;
    const uint32_t swzB1 = ((2 + cb) ^ xb) * 16;

    float* red = (float*)(smem_raw + STAGES * STAGE_B + 128);

    // fragment slots: s0 = kk0 of current chunk, s1 = kk1 of current chunk
    uint32_t a0[2][4], b0[4][4], a1[2][4], b1[4][4];

    // ---- prologue: issue chunks 0..2, preload kk0 of chunk 0 ----
    ISSUE(); ISSUE(); ISSUE();
    asm volatile("cp.async.wait_group 2;" ::: "memory");
    __syncthreads();
    {
        const uint32_t sS = sbase;   // stage 0
#pragma unroll
        for (int mt = 0; mt < 2; ++mt) ldm_x4(a0[mt], sS + aBase + mt * 1024 + swzA0);
#pragma unroll
        for (int np = 0; np < 4; ++np) ldm_x4(b0[np], sS + bBase + np * 1024 + swzB0);
    }

    int ch = 0;
    int g = cta;
#pragma unroll 1
    for (int t = 0; t < ntiles; ++t, g += NCTA) {
        float acc[2][8][4];
#pragma unroll
        for (int mt = 0; mt < 2; ++mt)
#pragma unroll
            for (int nt = 0; nt < 8; ++nt)
#pragma unroll
                for (int v = 0; v < 4; ++v) acc[mt][nt][v] = 0.0f;

#pragma unroll 1
        for (int it = 0; it < KITERS; ++it, ++ch) {
            const uint32_t sS = sbase + (uint32_t)(ch & 3) * STAGE_B;

            // load kk1 fragments of current chunk (not needed until mma s1)
#pragma unroll
            for (int mt = 0; mt < 2; ++mt) ldm_x4(a1[mt], sS + aBase + mt * 1024 + swzA1);
#pragma unroll
            for (int np = 0; np < 4; ++np) ldm_x4(b1[np], sS + bBase + np * 1024 + swzB1);

            // MMA on kk0 fragments (loaded one barrier ago) — hides the LDS burst
#pragma unroll
            for (int mt = 0; mt < 2; ++mt)
#pragma unroll
                for (int nt = 0; nt < 8; ++nt)
                    mma16816(acc[mt][nt], a0[mt], &b0[nt >> 1][(nt & 1) * 2]);

            if (ch + 1 < C) {
                // stage (ch+1) must be landed before loading its kk0 frags
                if (ch == C - 2) asm volatile("cp.async.wait_group 0;" ::: "memory");
                else             asm volatile("cp.async.wait_group 1;" ::: "memory");
                __syncthreads();
                if (issued < C) ISSUE();   // writes stage (ch+3)&3 == (ch-1)&3: free
                const uint32_t sN = sbase + (uint32_t)((ch + 1) & 3) * STAGE_B;
#pragma unroll
                for (int mt = 0; mt < 2; ++mt) ldm_x4(a0[mt], sN + aBase + mt * 1024 + swzA0);
#pragma unroll
                for (int np = 0; np < 4; ++np) ldm_x4(b0[np], sN + bBase + np * 1024 + swzB0);
            }

            // MMA on kk1 fragments (loaded at top of this iteration)
#pragma unroll
            for (int mt = 0; mt < 2; ++mt)
#pragma unroll
                for (int nt = 0; nt < 8; ++nt)
                    mma16816(acc[mt][nt], a1[mt], &b1[nt >> 1][(nt & 1) * 2]);
        }

        // ---- tile epilogue: softplus + deterministic reduction ----
        const float SCALE = 2.302585092994046f, BIAS = -10.0f;
        const int rowBase = (g >> 6) * BM;
        const int colBase = (g & 63) * BN;
        float lsum = 0.0f;
#pragma unroll
        for (int mt = 0; mt < 2; ++mt) {
            const int row0 = rowBase + warp_m * 32 + mt * 16 + (lane >> 2);
#pragma unroll
            for (int nt = 0; nt < 8; ++nt) {
                const int col0 = colBase + warp_n * 64 + nt * 8 + (lane & 3) * 2;
#pragma unroll
                for (int v = 0; v < 4; ++v) {
                    const int row = row0 + (v >> 1) * 8;
                    const int col = col0 + (v & 1);
                    float z = fmaf(acc[mt][nt][v], SCALE, BIAS);
                    if (row == col) z = -z;
                    lsum += fmaxf(z, 0.0f) + __logf(1.0f + __expf(-fabsf(z)));
                }
            }
        }
#pragma unroll
        for (int off = 16; off > 0; off >>= 1)
            lsum += __shfl_down_sync(0xFFFFFFFFu, lsum, off);
        if (lane == 0) red[wid] = lsum;
        __syncthreads();
        if (tid == 0) {
            float s = 0.0f;
#pragma unroll
            for (int i = 0; i < 16; ++i) s += red[i];
            g_partials[g] = s;
        }
        __syncthreads();
    }
#undef ISSUE

    // ---- last CTA out performs the deterministic finalize ----
    __threadfence();
    __syncthreads();
    if (tid == 0)
        s_last = (atomicAdd(&g_done, 1u) == NCTA - 1) ? 1u : 0u;
    __syncthreads();
    if (s_last) {
        __threadfence();
        double* sd = (double*)smem_raw;    // stage buffers dead
        double s = 0.0;
        for (int i = tid; i < NTILES; i += 512)
            s += (double)g_partials[i];
        sd[tid] = s;
        __syncthreads();
#pragma unroll
        for (int off = 256; off > 0; off >>= 1) {
            if (tid < off) sd[tid] += sd[tid + off];
            __syncthreads();
        }
        if (tid == 0) out[0] = (float)(sd[0] / (double)NN);
    }
}

extern "C" void kernel_launch(void* const* d_in, const int* in_sizes, int n_in,
                              void* d_out, int out_size) {
    cudaFuncSetAttribute(siglip_mma_kernel,
                         cudaFuncAttributeMaxDynamicSharedMemorySize, SMEM_TOTAL);
    convert_kernel<<<2048, 256>>>((const float*)d_in[0], (const float*)d_in[1]);
    siglip_mma_kernel<<<NCTA, 512, SMEM_TOTAL>>>((float*)d_out);
}

// round 7
// speedup vs baseline: 1.5872x; 1.5872x over previous
#include <cuda_runtime.h>
#include <cuda_bf16.h>
#include <cstdint>

// SigLipLoss: loss = (1/N) * sum_ij softplus(s_ij), sign-flip on diagonal.
// Round 6: persistent CTAs, 128x128 tiles, 256 threads, 2 CTAs/SM (grid 296)
// so two independent barrier domains per SM hide each other's LDS bursts.
// bf16 mma.sync, 4-stage cp.async pipeline, folded deterministic finalize.

#define NN 8192
#define DD 768
#define BM 128
#define BN 128
#define BK 32
#define NTILES (NN / BM * NN / BN)    // 4096
#define KITERS (DD / BK)              // 24
#define NCTA 296
#define ROWBYTES (DD * 2)             // 1536

#define A_B   (BM * 64)               // 8192
#define STAGE_B ((BM + BN) * 64)      // 16384
#define STAGES 4
#define SMEM_TOTAL (STAGES * STAGE_B + 256)

__device__ __align__(16) __nv_bfloat16 g_Abf[NN * DD];
__device__ __align__(16) __nv_bfloat16 g_Bbf[NN * DD];
__device__ float g_partials[NTILES];
__device__ unsigned g_done;

__device__ __forceinline__ uint32_t smem_u32(const void* p) {
    uint32_t r;
    asm("{ .reg .u64 t; cvta.to.shared.u64 t, %1; cvt.u32.u64 %0, t; }"
        : "=r"(r) : "l"(p));
    return r;
}
__device__ __forceinline__ void cpa16(uint32_t dst, const void* src) {
    asm volatile("cp.async.cg.shared.global [%0], [%1], 16;"
                 :: "r"(dst), "l"(__cvta_generic_to_global(src)) : "memory");
}
__device__ __forceinline__ void ldm_x4(uint32_t* r, uint32_t addr) {
    asm volatile("ldmatrix.sync.aligned.m8n8.x4.shared.b16 {%0,%1,%2,%3}, [%4];"
                 : "=r"(r[0]), "=r"(r[1]), "=r"(r[2]), "=r"(r[3]) : "r"(addr));
}
__device__ __forceinline__ void mma16816(float* c, const uint32_t* a,
                                         const uint32_t* b) {
    asm volatile(
        "mma.sync.aligned.m16n8k16.row.col.f32.bf16.bf16.f32 "
        "{%0,%1,%2,%3}, {%4,%5,%6,%7}, {%8,%9}, {%0,%1,%2,%3};"
        : "+f"(c[0]), "+f"(c[1]), "+f"(c[2]), "+f"(c[3])
        : "r"(a[0]), "r"(a[1]), "r"(a[2]), "r"(a[3]), "r"(b[0]), "r"(b[1]));
}

__global__ void convert_kernel(const float* __restrict__ A,
                               const float* __restrict__ B) {
    if (blockIdx.x == 0 && threadIdx.x == 0) g_done = 0;
    const int total4 = NN * DD / 4;
    const int stride = gridDim.x * blockDim.x;
    __nv_bfloat162* pa = (__nv_bfloat162*)g_Abf;
    __nv_bfloat162* pb = (__nv_bfloat162*)g_Bbf;
    for (int i = blockIdx.x * blockDim.x + threadIdx.x; i < total4; i += stride) {
        float4 a = ((const float4*)A)[i];
        float4 b = ((const float4*)B)[i];
        pa[2 * i + 0] = __floats2bfloat162_rn(a.x, a.y);
        pa[2 * i + 1] = __floats2bfloat162_rn(a.z, a.w);
        pb[2 * i + 0] = __floats2bfloat162_rn(b.x, b.y);
        pb[2 * i + 1] = __floats2bfloat162_rn(b.z, b.w);
    }
}

__global__ __launch_bounds__(256, 2) void siglip_mma_kernel(float* __restrict__ out) {
    extern __shared__ char smem_raw[];
    __shared__ unsigned s_last;
    uint32_t sbase = smem_u32(smem_raw);
    sbase = (sbase + 127u) & ~127u;

    const int tid  = threadIdx.x;
    const int wid  = tid >> 5;
    const int lane = tid & 31;
    const int warp_m = wid & 3;          // 4 m-groups of 32 rows
    const int warp_n = wid >> 2;         // 2 n-groups of 64 cols
    const int cta = blockIdx.x;

    const int ntiles = (NTILES - cta + NCTA - 1) / NCTA;
    const int C = ntiles * KITERS;

    // ---- producer mapping: 4x 16B per thread per chunk ----
    const int r0 = tid >> 2;             // 0..63
    const int c4 = tid & 3;
    const uint32_t swz = (uint32_t)((c4 ^ ((r0 >> 1) & 3)) * 16);
    const uint32_t dstA0 = r0 * 64 + swz;
    const uint32_t dstA1 = dstA0 + 64 * 64;
    const uint32_t dstB0 = A_B + r0 * 64 + swz;
    const uint32_t dstB1 = dstB0 + 64 * 64;
    const uint32_t cB16 = c4 * 16;

    int pKB = 0, pG = cta, issued = 0;
    const char* bA0 = (const char*)g_Abf
        + ((size_t)(pG >> 6) * BM + r0) * ROWBYTES + cB16;
    const char* bB0 = (const char*)g_Bbf
        + ((size_t)(pG & 63) * BN + r0) * ROWBYTES + cB16;

#define ISSUE() do {                                                     \
        const uint32_t stb = sbase + (uint32_t)(issued & 3) * STAGE_B;   \
        cpa16(stb + dstA0, bA0 + pKB);                                   \
        cpa16(stb + dstA1, bA0 + (size_t)64 * ROWBYTES + pKB);           \
        cpa16(stb + dstB0, bB0 + pKB);                                   \
        cpa16(stb + dstB1, bB0 + (size_t)64 * ROWBYTES + pKB);           \
        asm volatile("cp.async.commit_group;" ::: "memory");             \
        ++issued;                                                        \
        pKB += 64;                                                       \
        if (pKB == DD * 2) {                                             \
            pKB = 0; pG += NCTA;                                         \
            if (pG < NTILES) {                                           \
                bA0 = (const char*)g_Abf                                 \
                    + ((size_t)(pG >> 6) * BM + r0) * ROWBYTES + cB16;   \
                bB0 = (const char*)g_Bbf                                 \
                    + ((size_t)(pG & 63) * BN + r0) * ROWBYTES + cB16;   \
            }                                                            \
        }                                                                \
    } while (0)

    // ---- ldmatrix per-lane addresses (XOR swizzle) ----
    const int rowA = warp_m * 32 + (lane & 15);
    const uint32_t xa = (uint32_t)(((lane & 15) >> 1) & 3);
    const uint32_t ca = (uint32_t)(lane >> 4);
    const uint32_t aBase = rowA * 64;
    const uint32_t swzA0 = ((0 + ca) ^ xa) * 16;   // kk = 0
    const uint32_t swzA1 = ((2 + ca) ^ xa) * 16;   // kk = 1

    const int rowB = warp_n * 64 + (lane & 7) + ((lane >> 4) & 1) * 8;
    const uint32_t xb = (uint32_t)((rowB >> 1) & 3);
    const uint32_t cb = (uint32_t)((lane >> 3) & 1);
    const uint32_t bBase = A_B + rowB * 64;
    const uint32_t swzB0 = ((0 + cb) ^ xb) * 16;
    const uint32_t swzB1 = ((2 + cb) ^ xb) * 16;

    float* red = (float*)(smem_raw + STAGES * STAGE_B + 128);

    // prologue: fill 3 stages
    ISSUE(); ISSUE(); ISSUE();

    int ch = 0;
    int g = cta;
#pragma unroll 1
    for (int t = 0; t < ntiles; ++t, g += NCTA) {
        float acc[2][8][4];
#pragma unroll
        for (int mt = 0; mt < 2; ++mt)
#pragma unroll
            for (int nt = 0; nt < 8; ++nt)
#pragma unroll
                for (int v = 0; v < 4; ++v) acc[mt][nt][v] = 0.0f;

#pragma unroll 1
        for (int it = 0; it < KITERS; ++it, ++ch) {
            if (ch + 3 <= C) asm volatile("cp.async.wait_group 2;" ::: "memory");
            else             asm volatile("cp.async.wait_group 0;" ::: "memory");
            __syncthreads();
            if (issued < C) ISSUE();     // writes stage (ch+3)&3 == (ch-1)&3: free

            const uint32_t sS = sbase + (uint32_t)(ch & 3) * STAGE_B;
            uint32_t a[2][4], b[4][4];
#pragma unroll
            for (int kk = 0; kk < 2; ++kk) {
                const uint32_t sa = kk ? swzA1 : swzA0;
                const uint32_t sb = kk ? swzB1 : swzB0;
#pragma unroll
                for (int mt = 0; mt < 2; ++mt)
                    ldm_x4(a[mt], sS + aBase + mt * 1024 + sa);
#pragma unroll
                for (int np = 0; np < 4; ++np)
                    ldm_x4(b[np], sS + bBase + np * 1024 + sb);
#pragma unroll
                for (int mt = 0; mt < 2; ++mt)
#pragma unroll
                    for (int nt = 0; nt < 8; ++nt)
                        mma16816(acc[mt][nt], a[mt], &b[nt >> 1][(nt & 1) * 2]);
            }
        }

        // ---- tile epilogue: softplus + deterministic reduction ----
        const float SCALE = 2.302585092994046f, BIAS = -10.0f;
        const int rowBase = (g >> 6) * BM;
        const int colBase = (g & 63) * BN;
        float lsum = 0.0f;
#pragma unroll
        for (int mt = 0; mt < 2; ++mt) {
            const int row0 = rowBase + warp_m * 32 + mt * 16 + (lane >> 2);
#pragma unroll
            for (int nt = 0; nt < 8; ++nt) {
                const int col0 = colBase + warp_n * 64 + nt * 8 + (lane & 3) * 2;
#pragma unroll
                for (int v = 0; v < 4; ++v) {
                    const int row = row0 + (v >> 1) * 8;
                    const int col = col0 + (v & 1);
                    float z = fmaf(acc[mt][nt][v], SCALE, BIAS);
                    if (row == col) z = -z;
                    lsum += fmaxf(z, 0.0f) + __logf(1.0f + __expf(-fabsf(z)));
                }
            }
        }
#pragma unroll
        for (int off = 16; off > 0; off >>= 1)
            lsum += __shfl_down_sync(0xFFFFFFFFu, lsum, off);
        if (lane == 0) red[wid] = lsum;
        __syncthreads();
        if (tid == 0) {
            float s = 0.0f;
#pragma unroll
            for (int i = 0; i < 8; ++i) s += red[i];
            g_partials[g] = s;
        }
        __syncthreads();
    }
#undef ISSUE

    // ---- last CTA out performs the deterministic finalize ----
    __threadfence();
    __syncthreads();
    if (tid == 0)
        s_last = (atomicAdd(&g_done, 1u) == NCTA - 1) ? 1u : 0u;
    __syncthreads();
    if (s_last) {
        __threadfence();
        double* sd = (double*)smem_raw;    // stage buffers dead
        double s = 0.0;
        for (int i = tid; i < NTILES; i += 256)
            s += (double)g_partials[i];
        sd[tid] = s;
        __syncthreads();
#pragma unroll
        for (int off = 128; off > 0; off >>= 1) {
            if (tid < off) sd[tid] += sd[tid + off];
            __syncthreads();
        }
        if (tid == 0) out[0] = (float)(sd[0] / (double)NN);
    }
}

extern "C" void kernel_launch(void* const* d_in, const int* in_sizes, int n_in,
                              void* d_out, int out_size) {
    cudaFuncSetAttribute(siglip_mma_kernel,
                         cudaFuncAttributeMaxDynamicSharedMemorySize, SMEM_TOTAL);
    convert_kernel<<<2048, 256>>>((const float*)d_in[0], (const float*)d_in[1]);
    siglip_mma_kernel<<<NCTA, 256, SMEM_TOTAL>>>((float*)d_out);
}

// round 8
// speedup vs baseline: 1.7740x; 1.1177x over previous
#include <cuda_runtime.h>
#include <cuda_fp16.h>
#include <cstdint>

// SigLipLoss: loss = (1/N) * sum_ij softplus(s_ij), sign-flip on diagonal.
// Round 7: fp16 end-to-end (fp16 inputs, fp16-accum mma.sync) -> 32-reg
// accumulators free registers for cross-barrier ldmatrix/MMA software
// pipelining at 256 threads, 2 CTAs/SM. 4-stage cp.async pipeline.

#define NN 8192
#define DD 768
#define BM 128
#define BN 128
#define BK 32
#define NTILES (NN / BM * NN / BN)    // 4096
#define KITERS (DD / BK)              // 24
#define NCTA 296
#define ROWBYTES (DD * 2)             // 1536

#define A_B   (BM * 64)               // 8192
#define STAGE_B ((BM + BN) * 64)      // 16384
#define STAGES 4
#define SMEM_TOTAL (STAGES * STAGE_B + 256)

__device__ __align__(16) __half g_Ahf[NN * DD];
__device__ __align__(16) __half g_Bhf[NN * DD];
__device__ float g_partials[NTILES];
__device__ unsigned g_done;

__device__ __forceinline__ uint32_t smem_u32(const void* p) {
    uint32_t r;
    asm("{ .reg .u64 t; cvta.to.shared.u64 t, %1; cvt.u32.u64 %0, t; }"
        : "=r"(r) : "l"(p));
    return r;
}
__device__ __forceinline__ void cpa16(uint32_t dst, const void* src) {
    asm volatile("cp.async.cg.shared.global [%0], [%1], 16;"
                 :: "r"(dst), "l"(__cvta_generic_to_global(src)) : "memory");
}
__device__ __forceinline__ void ldm_x4(uint32_t* r, uint32_t addr) {
    asm volatile("ldmatrix.sync.aligned.m8n8.x4.shared.b16 {%0,%1,%2,%3}, [%4];"
                 : "=r"(r[0]), "=r"(r[1]), "=r"(r[2]), "=r"(r[3]) : "r"(addr));
}
__device__ __forceinline__ void mma16816h(uint32_t* c, const uint32_t* a,
                                          const uint32_t* b) {
    asm volatile(
        "mma.sync.aligned.m16n8k16.row.col.f16.f16.f16.f16 "
        "{%0,%1}, {%2,%3,%4,%5}, {%6,%7}, {%0,%1};"
        : "+r"(c[0]), "+r"(c[1])
        : "r"(a[0]), "r"(a[1]), "r"(a[2]), "r"(a[3]), "r"(b[0]), "r"(b[1]));
}

__global__ void convert_kernel(const float* __restrict__ A,
                               const float* __restrict__ B) {
    if (blockIdx.x == 0 && threadIdx.x == 0) g_done = 0;
    const int total4 = NN * DD / 4;
    const int stride = gridDim.x * blockDim.x;
    __half2* pa = (__half2*)g_Ahf;
    __half2* pb = (__half2*)g_Bhf;
    for (int i = blockIdx.x * blockDim.x + threadIdx.x; i < total4; i += stride) {
        float4 a = ((const float4*)A)[i];
        float4 b = ((const float4*)B)[i];
        pa[2 * i + 0] = __floats2half2_rn(a.x, a.y);
        pa[2 * i + 1] = __floats2half2_rn(a.z, a.w);
        pb[2 * i + 0] = __floats2half2_rn(b.x, b.y);
        pb[2 * i + 1] = __floats2half2_rn(b.z, b.w);
    }
}

__global__ __launch_bounds__(256, 2) void siglip_mma_kernel(float* __restrict__ out) {
    extern __shared__ char smem_raw[];
    __shared__ unsigned s_last;
    uint32_t sbase = smem_u32(smem_raw);
    sbase = (sbase + 127u) & ~127u;

    const int tid  = threadIdx.x;
    const int wid  = tid >> 5;
    const int lane = tid & 31;
    const int warp_m = wid & 3;          // 4 m-groups of 32 rows
    const int warp_n = wid >> 2;         // 2 n-groups of 64 cols
    const int cta = blockIdx.x;

    const int ntiles = (NTILES - cta + NCTA - 1) / NCTA;
    const int C = ntiles * KITERS;

    // ---- producer mapping: 4x 16B per thread per chunk ----
    const int r0 = tid >> 2;             // 0..63
    const int c4 = tid & 3;
    const uint32_t swz = (uint32_t)((c4 ^ ((r0 >> 1) & 3)) * 16);
    const uint32_t dstA0 = r0 * 64 + swz;
    const uint32_t dstA1 = dstA0 + 64 * 64;
    const uint32_t dstB0 = A_B + r0 * 64 + swz;
    const uint32_t dstB1 = dstB0 + 64 * 64;
    const uint32_t cB16 = c4 * 16;

    int pKB = 0, pG = cta, issued = 0;
    const char* bA0 = (const char*)g_Ahf
        + ((size_t)(pG >> 6) * BM + r0) * ROWBYTES + cB16;
    const char* bB0 = (const char*)g_Bhf
        + ((size_t)(pG & 63) * BN + r0) * ROWBYTES + cB16;

#define ISSUE() do {                                                     \
        const uint32_t stb = sbase + (uint32_t)(issued & 3) * STAGE_B;   \
        cpa16(stb + dstA0, bA0 + pKB);                                   \
        cpa16(stb + dstA1, bA0 + (size_t)64 * ROWBYTES + pKB);           \
        cpa16(stb + dstB0, bB0 + pKB);                                   \
        cpa16(stb + dstB1, bB0 + (size_t)64 * ROWBYTES + pKB);           \
        asm volatile("cp.async.commit_group;" ::: "memory");             \
        ++issued;                                                        \
        pKB += 64;                                                       \
        if (pKB == DD * 2) {                                             \
            pKB = 0; pG += NCTA;                                         \
            if (pG < NTILES) {                                           \
                bA0 = (const char*)g_Ahf                                 \
                    + ((size_t)(pG >> 6) * BM + r0) * ROWBYTES + cB16;   \
                bB0 = (const char*)g_Bhf                                 \
                    + ((size_t)(pG & 63) * BN + r0) * ROWBYTES + cB16;   \
            }                                                            \
        }                                                                \
    } while (0)

    // ---- ldmatrix per-lane addresses (XOR swizzle) ----
    const int rowA = warp_m * 32 + (lane & 15);
    const uint32_t xa = (uint32_t)(((lane & 15) >> 1) & 3);
    const uint32_t ca = (uint32_t)(lane >> 4);
    const uint32_t aBase = rowA * 64;
    const uint32_t swzA0 = ((0 + ca) ^ xa) * 16;   // kk = 0
    const uint32_t swzA1 = ((2 + ca) ^ xa) * 16;   // kk = 1

    const int rowB = warp_n * 64 + (lane & 7) + ((lane >> 4) & 1) * 8;
    const uint32_t xb = (uint32_t)((rowB >> 1) & 3);
    const uint32_t cb = (uint32_t)((lane >> 3) & 1);
    const uint32_t bBase = A_B + rowB * 64;
    const uint32_t swzB0 = ((0 + cb) ^ xb) * 16;
    const uint32_t swzB1 = ((2 + cb) ^ xb) * 16;

    float* red = (float*)(smem_raw + STAGES * STAGE_B + 128);

    // fragment slots: set0 = kk0 of current chunk, set1 = kk1 of current chunk
    uint32_t a0[2][4], b0[4][4], a1[2][4], b1[4][4];

    // ---- prologue ----
    ISSUE(); ISSUE(); ISSUE();
    asm volatile("cp.async.wait_group 2;" ::: "memory");
    __syncthreads();
    {
        const uint32_t sS = sbase;
#pragma unroll
        for (int mt = 0; mt < 2; ++mt) ldm_x4(a0[mt], sS + aBase + mt * 1024 + swzA0);
#pragma unroll
        for (int np = 0; np < 4; ++np) ldm_x4(b0[np], sS + bBase + np * 1024 + swzB0);
    }

    int ch = 0;
    int g = cta;
#pragma unroll 1
    for (int t = 0; t < ntiles; ++t, g += NCTA) {
        uint32_t acc[2][8][2];
#pragma unroll
        for (int mt = 0; mt < 2; ++mt)
#pragma unroll
            for (int nt = 0; nt < 8; ++nt) { acc[mt][nt][0] = 0u; acc[mt][nt][1] = 0u; }

#pragma unroll 1
        for (int it = 0; it < KITERS; ++it, ++ch) {
            const uint32_t sS = sbase + (uint32_t)(ch & 3) * STAGE_B;

            // load kk1 fragments of current chunk
#pragma unroll
            for (int mt = 0; mt < 2; ++mt) ldm_x4(a1[mt], sS + aBase + mt * 1024 + swzA1);
#pragma unroll
            for (int np = 0; np < 4; ++np) ldm_x4(b1[np], sS + bBase + np * 1024 + swzB1);

            // MMA on kk0 fragments (loaded one barrier ago)
#pragma unroll
            for (int mt = 0; mt < 2; ++mt)
#pragma unroll
                for (int nt = 0; nt < 8; ++nt)
                    mma16816h(acc[mt][nt], a0[mt], &b0[nt >> 1][(nt & 1) * 2]);

            if (ch + 1 < C) {
                if (ch == C - 2) asm volatile("cp.async.wait_group 0;" ::: "memory");
                else             asm volatile("cp.async.wait_group 1;" ::: "memory");
                __syncthreads();
                if (issued < C) ISSUE();   // writes stage (ch+3)&3 == (ch-1)&3: free
                const uint32_t sN = sbase + (uint32_t)((ch + 1) & 3) * STAGE_B;
#pragma unroll
                for (int mt = 0; mt < 2; ++mt) ldm_x4(a0[mt], sN + aBase + mt * 1024 + swzA0);
#pragma unroll
                for (int np = 0; np < 4; ++np) ldm_x4(b0[np], sN + bBase + np * 1024 + swzB0);
            }

            // MMA on kk1 fragments
#pragma unroll
            for (int mt = 0; mt < 2; ++mt)
#pragma unroll
                for (int nt = 0; nt < 8; ++nt)
                    mma16816h(acc[mt][nt], a1[mt], &b1[nt >> 1][(nt & 1) * 2]);
        }

        // ---- tile epilogue: softplus + deterministic reduction ----
        const float SCALE = 2.302585092994046f, BIAS = -10.0f;
        const int rowBase = (g >> 6) * BM;
        const int colBase = (g & 63) * BN;
        float lsum = 0.0f;
#pragma unroll
        for (int mt = 0; mt < 2; ++mt) {
            const int row0 = rowBase + warp_m * 32 + mt * 16 + (lane >> 2);
#pragma unroll
            for (int nt = 0; nt < 8; ++nt) {
                const int col0 = colBase + warp_n * 64 + nt * 8 + (lane & 3) * 2;
#pragma unroll
                for (int v = 0; v < 2; ++v) {
                    const int row = row0 + v * 8;
                    float2 f = __half22float2(*(const __half2*)&acc[mt][nt][v]);
                    float z0 = fmaf(f.x, SCALE, BIAS);
                    float z1 = fmaf(f.y, SCALE, BIAS);
                    if (row == col0)     z0 = -z0;
                    if (row == col0 + 1) z1 = -z1;
                    lsum += fmaxf(z0, 0.0f) + __logf(1.0f + __expf(-fabsf(z0)));
                    lsum += fmaxf(z1, 0.0f) + __logf(1.0f + __expf(-fabsf(z1)));
                }
            }
        }
#pragma unroll
        for (int off = 16; off > 0; off >>= 1)
            lsum += __shfl_down_sync(0xFFFFFFFFu, lsum, off);
        if (lane == 0) red[wid] = lsum;
        __syncthreads();
        if (tid == 0) {
            float s = 0.0f;
#pragma unroll
            for (int i = 0; i < 8; ++i) s += red[i];
            g_partials[g] = s;
        }
        __syncthreads();
    }
#undef ISSUE

    // ---- last CTA out performs the deterministic finalize ----
    __threadfence();
    __syncthreads();
    if (tid == 0)
        s_last = (atomicAdd(&g_done, 1u) == NCTA - 1) ? 1u : 0u;
    __syncthreads();
    if (s_last) {
        __threadfence();
        double* sd = (double*)smem_raw;    // stage buffers dead
        double s = 0.0;
        for (int i = tid; i < NTILES; i += 256)
            s += (double)g_partials[i];
        sd[tid] = s;
        __syncthreads();
#pragma unroll
        for (int off = 128; off > 0; off >>= 1) {
            if (tid < off) sd[tid] += sd[tid + off];
            __syncthreads();
        }
        if (tid == 0) out[0] = (float)(sd[0] / (double)NN);
    }
}

extern "C" void kernel_launch(void* const* d_in, const int* in_sizes, int n_in,
                              void* d_out, int out_size) {
    cudaFuncSetAttribute(siglip_mma_kernel,
                         cudaFuncAttributeMaxDynamicSharedMemorySize, SMEM_TOTAL);
    convert_kernel<<<2048, 256>>>((const float*)d_in[0], (const float*)d_in[1]);
    siglip_mma_kernel<<<NCTA, 256, SMEM_TOTAL>>>((float*)d_out);
}

// round 9
// speedup vs baseline: 1.8551x; 1.0457x over previous
#include <cuda_runtime.h>
#include <cuda_fp16.h>
#include <cstdint>

// SigLipLoss: loss = (1/N) * sum_ij softplus(s_ij), sign-flip on diagonal.
// Round 8: 128x256 CTA tile, warp tile 64x64 (rm2 x rn4) -> LDSM traffic
// 0.086 B/MAC (was 0.125) so the smem crossbar is no longer co-binding with
// the tensor pipe. fp16 end-to-end mma.sync, 2 CTAs/SM, 4-stage cp.async.

#define NN 8192
#define DD 768
#define BM 128
#define BN 256
#define BK 32
#define NROWT (NN / BM)               // 64
#define NCOLT (NN / BN)               // 32
#define NTILES (NROWT * NCOLT)        // 2048
#define KITERS (DD / BK)              // 24
#define NCTA 296
#define ROWBYTES (DD * 2)             // 1536

#define A_B   (BM * 64)               // 8192
#define STAGE_B ((BM + BN) * 64)      // 24576
#define STAGES 4
#define SMEM_TOTAL (STAGES * STAGE_B + 256)

__device__ __align__(16) __half g_Ahf[NN * DD];
__device__ __align__(16) __half g_Bhf[NN * DD];
__device__ float g_partials[NTILES];
__device__ unsigned g_done;

__device__ __forceinline__ uint32_t smem_u32(const void* p) {
    uint32_t r;
    asm("{ .reg .u64 t; cvta.to.shared.u64 t, %1; cvt.u32.u64 %0, t; }"
        : "=r"(r) : "l"(p));
    return r;
}
__device__ __forceinline__ void cpa16(uint32_t dst, const void* src) {
    asm volatile("cp.async.cg.shared.global [%0], [%1], 16;"
                 :: "r"(dst), "l"(__cvta_generic_to_global(src)) : "memory");
}
__device__ __forceinline__ void ldm_x4(uint32_t* r, uint32_t addr) {
    asm volatile("ldmatrix.sync.aligned.m8n8.x4.shared.b16 {%0,%1,%2,%3}, [%4];"
                 : "=r"(r[0]), "=r"(r[1]), "=r"(r[2]), "=r"(r[3]) : "r"(addr));
}
__device__ __forceinline__ void mma16816h(uint32_t* c, const uint32_t* a,
                                          const uint32_t* b) {
    asm volatile(
        "mma.sync.aligned.m16n8k16.row.col.f16.f16.f16.f16 "
        "{%0,%1}, {%2,%3,%4,%5}, {%6,%7}, {%0,%1};"
        : "+r"(c[0]), "+r"(c[1])
        : "r"(a[0]), "r"(a[1]), "r"(a[2]), "r"(a[3]), "r"(b[0]), "r"(b[1]));
}

__global__ void convert_kernel(const float* __restrict__ A,
                               const float* __restrict__ B) {
    if (blockIdx.x == 0 && threadIdx.x == 0) g_done = 0;
    const int total4 = NN * DD / 4;
    const int stride = gridDim.x * blockDim.x;
    __half2* pa = (__half2*)g_Ahf;
    __half2* pb = (__half2*)g_Bhf;
    for (int i = blockIdx.x * blockDim.x + threadIdx.x; i < total4; i += stride) {
        float4 a = ((const float4*)A)[i];
        float4 b = ((const float4*)B)[i];
        pa[2 * i + 0] = __floats2half2_rn(a.x, a.y);
        pa[2 * i + 1] = __floats2half2_rn(a.z, a.w);
        pb[2 * i + 0] = __floats2half2_rn(b.x, b.y);
        pb[2 * i + 1] = __floats2half2_rn(b.z, b.w);
    }
}

__global__ __launch_bounds__(256, 2) void siglip_mma_kernel(float* __restrict__ out) {
    extern __shared__ char smem_raw[];
    __shared__ unsigned s_last;
    uint32_t sbase = smem_u32(smem_raw);
    sbase = (sbase + 127u) & ~127u;

    const int tid  = threadIdx.x;
    const int wid  = tid >> 5;
    const int lane = tid & 31;
    const int warp_m = wid & 1;          // 2 m-groups of 64 rows
    const int warp_n = wid >> 1;         // 4 n-groups of 64 cols
    const int cta = blockIdx.x;

    const int ntiles = (NTILES - cta + NCTA - 1) / NCTA;
    const int C = ntiles * KITERS;

    // ---- producer mapping: 6x 16B per thread per chunk (A:2, B:4) ----
    const int r0 = tid >> 2;             // 0..63
    const int c4 = tid & 3;
    const uint32_t swz = (uint32_t)((c4 ^ ((r0 >> 1) & 3)) * 16);
    const uint32_t dstA = r0 * 64 + swz;           // rows r0, r0+64
    const uint32_t dstB = A_B + r0 * 64 + swz;     // rows r0, +64, +128, +192
    const uint32_t cB16 = c4 * 16;

    int pKB = 0, pG = cta, issued = 0;
    const char* bA0 = (const char*)g_Ahf
        + ((size_t)(pG >> 5) * BM + r0) * ROWBYTES + cB16;
    const char* bB0 = (const char*)g_Bhf
        + ((size_t)(pG & 31) * BN + r0) * ROWBYTES + cB16;

#define ISSUE() do {                                                     \
        const uint32_t stb = sbase + (uint32_t)(issued & 3) * STAGE_B;   \
        cpa16(stb + dstA,            bA0 + pKB);                         \
        cpa16(stb + dstA + 64 * 64,  bA0 + (size_t)64 * ROWBYTES + pKB); \
        cpa16(stb + dstB,            bB0 + pKB);                         \
        cpa16(stb + dstB + 64 * 64,  bB0 + (size_t)64  * ROWBYTES + pKB);\
        cpa16(stb + dstB + 128 * 64, bB0 + (size_t)128 * ROWBYTES + pKB);\
        cpa16(stb + dstB + 192 * 64, bB0 + (size_t)192 * ROWBYTES + pKB);\
        asm volatile("cp.async.commit_group;" ::: "memory");             \
        ++issued;                                                        \
        pKB += 64;                                                       \
        if (pKB == DD * 2) {                                             \
            pKB = 0; pG += NCTA;                                         \
            if (pG < NTILES) {                                           \
                bA0 = (const char*)g_Ahf                                 \
                    + ((size_t)(pG >> 5) * BM + r0) * ROWBYTES + cB16;   \
                bB0 = (const char*)g_Bhf                                 \
                    + ((size_t)(pG & 31) * BN + r0) * ROWBYTES + cB16;   \
            }                                                            \
        }                                                                \
    } while (0)

    // ---- ldmatrix per-lane addresses (XOR swizzle on 64B rows) ----
    const int rowA = warp_m * 64 + (lane & 15);
    const uint32_t xa = (uint32_t)(((lane & 15) >> 1) & 3);
    const uint32_t ca = (uint32_t)(lane >> 4);
    const uint32_t aBase = rowA * 64;
    const uint32_t swzA0 = ((0 + ca) ^ xa) * 16;   // kk = 0
    const uint32_t swzA1 = ((2 + ca) ^ xa) * 16;   // kk = 1

    const int rowB = warp_n * 64 + (lane & 7) + ((lane >> 4) & 1) * 8;
    const uint32_t xb = (uint32_t)((rowB >> 1) & 3);
    const uint32_t cb = (uint32_t)((lane >> 3) & 1);
    const uint32_t bBase = A_B + rowB * 64;
    const uint32_t swzB0 = ((0 + cb) ^ xb) * 16;
    const uint32_t swzB1 = ((2 + cb) ^ xb) * 16;

    float* red = (float*)(smem_raw + STAGES * STAGE_B + 128);

    // prologue: fill 3 stages
    ISSUE(); ISSUE(); ISSUE();

    int ch = 0;
    int g = cta;
#pragma unroll 1
    for (int t = 0; t < ntiles; ++t, g += NCTA) {
        uint32_t acc[4][8][2];
#pragma unroll
        for (int mt = 0; mt < 4; ++mt)
#pragma unroll
            for (int nt = 0; nt < 8; ++nt) { acc[mt][nt][0] = 0u; acc[mt][nt][1] = 0u; }

#pragma unroll 1
        for (int it = 0; it < KITERS; ++it, ++ch) {
            if (ch + 3 <= C) asm volatile("cp.async.wait_group 2;" ::: "memory");
            else             asm volatile("cp.async.wait_group 0;" ::: "memory");
            __syncthreads();
            if (issued < C) ISSUE();     // writes stage (ch+3)&3 == (ch-1)&3: free

            const uint32_t sS = sbase + (uint32_t)(ch & 3) * STAGE_B;
#pragma unroll
            for (int kk = 0; kk < 2; ++kk) {
                const uint32_t sa = kk ? swzA1 : swzA0;
                const uint32_t sb = kk ? swzB1 : swzB0;
                uint32_t a[4][4], b[4][4];
#pragma unroll
                for (int mt = 0; mt < 4; ++mt)
                    ldm_x4(a[mt], sS + aBase + mt * 1024 + sa);
#pragma unroll
                for (int np = 0; np < 4; ++np)
                    ldm_x4(b[np], sS + bBase + np * 1024 + sb);
#pragma unroll
                for (int mt = 0; mt < 4; ++mt)
#pragma unroll
                    for (int nt = 0; nt < 8; ++nt)
                        mma16816h(acc[mt][nt], a[mt], &b[nt >> 1][(nt & 1) * 2]);
            }
        }

        // ---- tile epilogue: softplus + deterministic reduction ----
        const float SCALE = 2.302585092994046f, BIAS = -10.0f;
        const int rowBase = (g >> 5) * BM;
        const int colBase = (g & 31) * BN;
        float lsum = 0.0f;
#pragma unroll
        for (int mt = 0; mt < 4; ++mt) {
            const int row0 = rowBase + warp_m * 64 + mt * 16 + (lane >> 2);
#pragma unroll
            for (int nt = 0; nt < 8; ++nt) {
                const int col0 = colBase + warp_n * 64 + nt * 8 + (lane & 3) * 2;
#pragma unroll
                for (int v = 0; v < 2; ++v) {
                    const int row = row0 + v * 8;
                    float2 f = __half22float2(*(const __half2*)&acc[mt][nt][v]);
                    float z0 = fmaf(f.x, SCALE, BIAS);
                    float z1 = fmaf(f.y, SCALE, BIAS);
                    if (row == col0)     z0 = -z0;
                    if (row == col0 + 1) z1 = -z1;
                    lsum += fmaxf(z0, 0.0f) + __logf(1.0f + __expf(-fabsf(z0)));
                    lsum += fmaxf(z1, 0.0f) + __logf(1.0f + __expf(-fabsf(z1)));
                }
            }
        }
#pragma unroll
        for (int off = 16; off > 0; off >>= 1)
            lsum += __shfl_down_sync(0xFFFFFFFFu, lsum, off);
        if (lane == 0) red[wid] = lsum;
        __syncthreads();
        if (tid == 0) {
            float s = 0.0f;
#pragma unroll
            for (int i = 0; i < 8; ++i) s += red[i];
            g_partials[g] = s;
        }
        __syncthreads();
    }
#undef ISSUE

    // ---- last CTA out performs the deterministic finalize ----
    __threadfence();
    __syncthreads();
    if (tid == 0)
        s_last = (atomicAdd(&g_done, 1u) == NCTA - 1) ? 1u : 0u;
    __syncthreads();
    if (s_last) {
        __threadfence();
        double* sd = (double*)smem_raw;    // stage buffers dead
        double s = 0.0;
        for (int i = tid; i < NTILES; i += 256)
            s += (double)g_partials[i];
        sd[tid] = s;
        __syncthreads();
#pragma unroll
        for (int off = 128; off > 0; off >>= 1) {
            if (tid < off) sd[tid] += sd[tid + off];
            __syncthreads();
        }
        if (tid == 0) out[0] = (float)(sd[0] / (double)NN);
    }
}

extern "C" void kernel_launch(void* const* d_in, const int* in_sizes, int n_in,
                              void* d_out, int out_size) {
    cudaFuncSetAttribute(siglip_mma_kernel,
                         cudaFuncAttributeMaxDynamicSharedMemorySize, SMEM_TOTAL);
    convert_kernel<<<2048, 256>>>((const float*)d_in[0], (const float*)d_in[1]);
    siglip_mma_kernel<<<NCTA, 256, SMEM_TOTAL>>>((float*)d_out);
}

// round 10
// speedup vs baseline: 2.0558x; 1.1082x over previous
#include <cuda_runtime.h>
#include <cuda_fp16.h>
#include <cstdint>

// SigLipLoss: loss = (1/N) * sum_ij softplus(s_ij), sign-flip on diagonal.
// Round 9: certify-one-ahead barrier placement -> the block barrier is
// crossed with kk1 fragments already in registers, so every post-barrier
// instruction is MMA (no synchronized LDSM burst). Zero extra registers.
// 128x256 tile, warp 64x64, fp16 mma.sync, 2 CTAs/SM, 4-stage cp.async.
// Epilogue: grouped log-products (16 logs + 128 exps per thread, was 128+128).

#define NN 8192
#define DD 768
#define BM 128
#define BN 256
#define BK 32
#define NROWT (NN / BM)               // 64
#define NCOLT (NN / BN)               // 32
#define NTILES (NROWT * NCOLT)        // 2048
#define KITERS (DD / BK)              // 24
#define NCTA 296
#define ROWBYTES (DD * 2)             // 1536

#define A_B   (BM * 64)               // 8192
#define STAGE_B ((BM + BN) * 64)      // 24576
#define STAGES 4
#define SMEM_TOTAL (STAGES * STAGE_B + 256)

__device__ __align__(16) __half g_Ahf[NN * DD];
__device__ __align__(16) __half g_Bhf[NN * DD];
__device__ float g_partials[NTILES];
__device__ unsigned g_done;

__device__ __forceinline__ uint32_t smem_u32(const void* p) {
    uint32_t r;
    asm("{ .reg .u64 t; cvta.to.shared.u64 t, %1; cvt.u32.u64 %0, t; }"
        : "=r"(r) : "l"(p));
    return r;
}
__device__ __forceinline__ void cpa16(uint32_t dst, const void* src) {
    asm volatile("cp.async.cg.shared.global [%0], [%1], 16;"
                 :: "r"(dst), "l"(__cvta_generic_to_global(src)) : "memory");
}
__device__ __forceinline__ void ldm_x4(uint32_t* r, uint32_t addr) {
    asm volatile("ldmatrix.sync.aligned.m8n8.x4.shared.b16 {%0,%1,%2,%3}, [%4];"
                 : "=r"(r[0]), "=r"(r[1]), "=r"(r[2]), "=r"(r[3]) : "r"(addr));
}
__device__ __forceinline__ void mma16816h(uint32_t* c, const uint32_t* a,
                                          const uint32_t* b) {
    asm volatile(
        "mma.sync.aligned.m16n8k16.row.col.f16.f16.f16.f16 "
        "{%0,%1}, {%2,%3,%4,%5}, {%6,%7}, {%0,%1};"
        : "+r"(c[0]), "+r"(c[1])
        : "r"(a[0]), "r"(a[1]), "r"(a[2]), "r"(a[3]), "r"(b[0]), "r"(b[1]));
}

__global__ void convert_kernel(const float* __restrict__ A,
                               const float* __restrict__ B) {
    if (blockIdx.x == 0 && threadIdx.x == 0) g_done = 0;
    const int total4 = NN * DD / 4;
    const int stride = gridDim.x * blockDim.x;
    __half2* pa = (__half2*)g_Ahf;
    __half2* pb = (__half2*)g_Bhf;
    for (int i = blockIdx.x * blockDim.x + threadIdx.x; i < total4; i += stride) {
        float4 a = ((const float4*)A)[i];
        float4 b = ((const float4*)B)[i];
        pa[2 * i + 0] = __floats2half2_rn(a.x, a.y);
        pa[2 * i + 1] = __floats2half2_rn(a.z, a.w);
        pb[2 * i + 0] = __floats2half2_rn(b.x, b.y);
        pb[2 * i + 1] = __floats2half2_rn(b.z, b.w);
    }
}

__global__ __launch_bounds__(256, 2) void siglip_mma_kernel(float* __restrict__ out) {
    extern __shared__ char smem_raw[];
    __shared__ unsigned s_last;
    uint32_t sbase = smem_u32(smem_raw);
    sbase = (sbase + 127u) & ~127u;

    const int tid  = threadIdx.x;
    const int wid  = tid >> 5;
    const int lane = tid & 31;
    const int warp_m = wid & 1;          // 2 m-groups of 64 rows
    const int warp_n = wid >> 1;         // 4 n-groups of 64 cols
    const int cta = blockIdx.x;

    const int ntiles = (NTILES - cta + NCTA - 1) / NCTA;
    const int C = ntiles * KITERS;

    // ---- producer mapping: 6x 16B per thread per chunk (A:2, B:4) ----
    const int r0 = tid >> 2;             // 0..63
    const int c4 = tid & 3;
    const uint32_t swz = (uint32_t)((c4 ^ ((r0 >> 1) & 3)) * 16);
    const uint32_t dstA = r0 * 64 + swz;
    const uint32_t dstB = A_B + r0 * 64 + swz;
    const uint32_t cB16 = c4 * 16;

    int pKB = 0, pG = cta, issued = 0;
    const char* bA0 = (const char*)g_Ahf
        + ((size_t)(pG >> 5) * BM + r0) * ROWBYTES + cB16;
    const char* bB0 = (const char*)g_Bhf
        + ((size_t)(pG & 31) * BN + r0) * ROWBYTES + cB16;

#define ISSUE() do {                                                     \
        const uint32_t stb = sbase + (uint32_t)(issued & 3) * STAGE_B;   \
        cpa16(stb + dstA,            bA0 + pKB);                         \
        cpa16(stb + dstA + 64 * 64,  bA0 + (size_t)64 * ROWBYTES + pKB); \
        cpa16(stb + dstB,            bB0 + pKB);                         \
        cpa16(stb + dstB + 64 * 64,  bB0 + (size_t)64  * ROWBYTES + pKB);\
        cpa16(stb + dstB + 128 * 64, bB0 + (size_t)128 * ROWBYTES + pKB);\
        cpa16(stb + dstB + 192 * 64, bB0 + (size_t)192 * ROWBYTES + pKB);\
        asm volatile("cp.async.commit_group;" ::: "memory");             \
        ++issued;                                                        \
        pKB += 64;                                                       \
        if (pKB == DD * 2) {                                             \
            pKB = 0; pG += NCTA;                                         \
            if (pG < NTILES) {                                           \
                bA0 = (const char*)g_Ahf                                 \
                    + ((size_t)(pG >> 5) * BM + r0) * ROWBYTES + cB16;   \
                bB0 = (const char*)g_Bhf                                 \
                    + ((size_t)(pG & 31) * BN + r0) * ROWBYTES + cB16;   \
            }                                                            \
        }                                                                \
    } while (0)

    // ---- ldmatrix per-lane addresses (XOR swizzle on 64B rows) ----
    const int rowA = warp_m * 64 + (lane & 15);
    const uint32_t xa = (uint32_t)(((lane & 15) >> 1) & 3);
    const uint32_t ca = (uint32_t)(lane >> 4);
    const uint32_t aBase = rowA * 64;
    const uint32_t swzA0 = ((0 + ca) ^ xa) * 16;   // kk = 0
    const uint32_t swzA1 = ((2 + ca) ^ xa) * 16;   // kk = 1

    const int rowB = warp_n * 64 + (lane & 7) + ((lane >> 4) & 1) * 8;
    const uint32_t xb = (uint32_t)((rowB >> 1) & 3);
    const uint32_t cb = (uint32_t)((lane >> 3) & 1);
    const uint32_t bBase = A_B + rowB * 64;
    const uint32_t swzB0 = ((0 + cb) ^ xb) * 16;
    const uint32_t swzB1 = ((2 + cb) ^ xb) * 16;

    float* red = (float*)(smem_raw + STAGES * STAGE_B + 128);

    // ---- prologue: fill all 4 stages, certify chunk 0 block-wide ----
    ISSUE(); ISSUE(); ISSUE(); ISSUE();
    asm volatile("cp.async.wait_group 3;" ::: "memory");
    __syncthreads();

    int ch = 0;
    int g = cta;
#pragma unroll 1
    for (int t = 0; t < ntiles; ++t, g += NCTA) {
        uint32_t acc[4][8][2];
#pragma unroll
        for (int mt = 0; mt < 4; ++mt)
#pragma unroll
            for (int nt = 0; nt < 8; ++nt) { acc[mt][nt][0] = 0u; acc[mt][nt][1] = 0u; }

#pragma unroll 1
        for (int it = 0; it < KITERS; ++it, ++ch) {
            // stage ch&3 was certified by the barrier of the PREVIOUS iteration
            const uint32_t sS = sbase + (uint32_t)(ch & 3) * STAGE_B;
            uint32_t a[4][4], b[4][4];

            // kk0: load + MMA
#pragma unroll
            for (int mt = 0; mt < 4; ++mt)
                ldm_x4(a[mt], sS + aBase + mt * 1024 + swzA0);
#pragma unroll
            for (int np = 0; np < 4; ++np)
                ldm_x4(b[np], sS + bBase + np * 1024 + swzB0);
#pragma unroll
            for (int mt = 0; mt < 4; ++mt)
#pragma unroll
                for (int nt = 0; nt < 8; ++nt)
                    mma16816h(acc[mt][nt], a[mt], &b[nt >> 1][(nt & 1) * 2]);

            // kk1: load fragments (they survive the barrier in registers)
#pragma unroll
            for (int mt = 0; mt < 4; ++mt)
                ldm_x4(a[mt], sS + aBase + mt * 1024 + swzA1);
#pragma unroll
            for (int np = 0; np < 4; ++np)
                ldm_x4(b[np], sS + bBase + np * 1024 + swzB1);

            // certify chunk ch+1 block-wide; quiesce readers of stage ch&3
            if (ch + 4 <= C)      asm volatile("cp.async.wait_group 2;" ::: "memory");
            else if (ch + 3 == C) asm volatile("cp.async.wait_group 1;" ::: "memory");
            else                  asm volatile("cp.async.wait_group 0;" ::: "memory");
            __syncthreads();
            if (issued < C) ISSUE();   // writes stage (ch+4)&3 == ch&3: just freed

            // kk1 MMA: pure tensor work flowing out of the barrier
#pragma unroll
            for (int mt = 0; mt < 4; ++mt)
#pragma unroll
                for (int nt = 0; nt < 8; ++nt)
                    mma16816h(acc[mt][nt], a[mt], &b[nt >> 1][(nt & 1) * 2]);
        }

        // ---- tile epilogue: softplus via grouped log-products ----
        const float SCALE = 2.302585092994046f, BIAS = -10.0f;
        const int rowBase = (g >> 5) * BM;
        const int colBase = (g & 31) * BN;
        float lsum = 0.0f;
#pragma unroll
        for (int mt = 0; mt < 4; ++mt) {
            const int row0 = rowBase + warp_m * 64 + mt * 16 + (lane >> 2);
#pragma unroll
            for (int ntp = 0; ntp < 4; ++ntp) {
                float prod = 1.0f;
#pragma unroll
                for (int h = 0; h < 2; ++h) {
                    const int nt = ntp * 2 + h;
                    const int col0 = colBase + warp_n * 64 + nt * 8 + (lane & 3) * 2;
#pragma unroll
                    for (int v = 0; v < 2; ++v) {
                        const int row = row0 + v * 8;
                        float2 f = __half22float2(*(const __half2*)&acc[mt][nt][v]);
                        float z0 = fmaf(f.x, SCALE, BIAS);
                        float z1 = fmaf(f.y, SCALE, BIAS);
                        if (row == col0)     z0 = -z0;
                        if (row == col0 + 1) z1 = -z1;
                        lsum += fmaxf(z0, 0.0f) + fmaxf(z1, 0.0f);
                        // factors in (1,2]: product of 8 <= 256, no overflow
                        prod *= (1.0f + __expf(-fabsf(z0)))
                              * (1.0f + __expf(-fabsf(z1)));
                    }
                }
                lsum += __logf(prod);
            }
        }
#pragma unroll
        for (int off = 16; off > 0; off >>= 1)
            lsum += __shfl_down_sync(0xFFFFFFFFu, lsum, off);
        if (lane == 0) red[wid] = lsum;
        __syncthreads();
        if (tid == 0) {
            float s = 0.0f;
#pragma unroll
            for (int i = 0; i < 8; ++i) s += red[i];
            g_partials[g] = s;
        }
        __syncthreads();
    }
#undef ISSUE

    // ---- last CTA out performs the deterministic finalize ----
    __threadfence();
    __syncthreads();
    if (tid == 0)
        s_last = (atomicAdd(&g_done, 1u) == NCTA - 1) ? 1u : 0u;
    __syncthreads();
    if (s_last) {
        __threadfence();
        double* sd = (double*)smem_raw;    // stage buffers dead
        double s = 0.0;
        for (int i = tid; i < NTILES; i += 256)
            s += (double)g_partials[i];
        sd[tid] = s;
        __syncthreads();
#pragma unroll
        for (int off = 128; off > 0; off >>= 1) {
            if (tid < off) sd[tid] += sd[tid + off];
            __syncthreads();
        }
        if (tid == 0) out[0] = (float)(sd[0] / (double)NN);
    }
}

extern "C" void kernel_launch(void* const* d_in, const int* in_sizes, int n_in,
                              void* d_out, int out_size) {
    cudaFuncSetAttribute(siglip_mma_kernel,
                         cudaFuncAttributeMaxDynamicSharedMemorySize, SMEM_TOTAL);
    convert_kernel<<<2048, 256>>>((const float*)d_in[0], (const float*)d_in[1]);
    siglip_mma_kernel<<<NCTA, 256, SMEM_TOTAL>>>((float*)d_out);
}

// round 12
// speedup vs baseline: 2.0713x; 1.0075x over previous
#include <cuda_runtime.h>
#include <cuda_fp16.h>
#include <cstdint>

// SigLipLoss: loss = (1/N) * sum_ij softplus(s_ij), sign-flip on diagonal.
// Round 11 (= R10 with h2exp2 name collision fixed): BK=64 / 2-stage pipeline
// (half the barriers), certify-one-ahead (kk3 frags cross the barrier in
// registers), de-synchronized per-warp epilogue (no syncthreads, partials
// straight to global), fp16x2 softplus with ex2.approx.f16x2, diagonal as
// exact -z correction.

#define NN 8192
#define DD 768
#define BM 128
#define BN 256
#define BK 64
#define NROWT (NN / BM)               // 64
#define NCOLT (NN / BN)               // 32
#define NTILES (NROWT * NCOLT)        // 2048
#define KITERS (DD / BK)              // 12
#define NCTA 296
#define ROWBYTES (DD * 2)             // 1536

#define A_B   (BM * 128)              // 16384
#define STAGE_B ((BM + BN) * 128)     // 49152
#define SMEM_TOTAL (2 * STAGE_B + 128)

__device__ __align__(16) __half g_Ahf[NN * DD];
__device__ __align__(16) __half g_Bhf[NN * DD];
__device__ float g_partials8[NTILES * 8];
__device__ unsigned g_done;

__device__ __forceinline__ uint32_t smem_u32(const void* p) {
    uint32_t r;
    asm("{ .reg .u64 t; cvta.to.shared.u64 t, %1; cvt.u32.u64 %0, t; }"
        : "=r"(r) : "l"(p));
    return r;
}
__device__ __forceinline__ void cpa16(uint32_t dst, const void* src) {
    asm volatile("cp.async.cg.shared.global [%0], [%1], 16;"
                 :: "r"(dst), "l"(__cvta_generic_to_global(src)) : "memory");
}
__device__ __forceinline__ void ldm_x4(uint32_t* r, uint32_t addr) {
    asm volatile("ldmatrix.sync.aligned.m8n8.x4.shared.b16 {%0,%1,%2,%3}, [%4];"
                 : "=r"(r[0]), "=r"(r[1]), "=r"(r[2]), "=r"(r[3]) : "r"(addr));
}
__device__ __forceinline__ void mma16816h(uint32_t* c, const uint32_t* a,
                                          const uint32_t* b) {
    asm volatile(
        "mma.sync.aligned.m16n8k16.row.col.f16.f16.f16.f16 "
        "{%0,%1}, {%2,%3,%4,%5}, {%6,%7}, {%0,%1};"
        : "+r"(c[0]), "+r"(c[1])
        : "r"(a[0]), "r"(a[1]), "r"(a[2]), "r"(a[3]), "r"(b[0]), "r"(b[1]));
}
__device__ __forceinline__ __half2 sp_h2exp2(__half2 x) {
    uint32_t r, xi = *(uint32_t*)&x;
    asm("ex2.approx.f16x2 %0, %1;" : "=r"(r) : "r"(xi));
    return *(__half2*)&r;
}

__global__ void convert_kernel(const float* __restrict__ A,
                               const float* __restrict__ B) {
    if (blockIdx.x == 0 && threadIdx.x == 0) g_done = 0;
    const int total4 = NN * DD / 4;
    const int stride = gridDim.x * blockDim.x;
    __half2* pa = (__half2*)g_Ahf;
    __half2* pb = (__half2*)g_Bhf;
    for (int i = blockIdx.x * blockDim.x + threadIdx.x; i < total4; i += stride) {
        float4 a = ((const float4*)A)[i];
        float4 b = ((const float4*)B)[i];
        pa[2 * i + 0] = __floats2half2_rn(a.x, a.y);
        pa[2 * i + 1] = __floats2half2_rn(a.z, a.w);
        pb[2 * i + 0] = __floats2half2_rn(b.x, b.y);
        pb[2 * i + 1] = __floats2half2_rn(b.z, b.w);
    }
}

__global__ __launch_bounds__(256, 2) void siglip_mma_kernel(float* __restrict__ out) {
    extern __shared__ char smem_raw[];
    __shared__ unsigned s_last;
    uint32_t sbase = smem_u32(smem_raw);
    sbase = (sbase + 127u) & ~127u;

    const int tid  = threadIdx.x;
    const int wid  = tid >> 5;
    const int lane = tid & 31;
    const int warp_m = wid & 1;          // 2 m-groups of 64 rows
    const int warp_n = wid >> 1;         // 4 n-groups of 64 cols
    const int cta = blockIdx.x;

    const int ntiles = (NTILES - cta + NCTA - 1) / NCTA;
    const int C = ntiles * KITERS;

    // ---- producer mapping: 12x 16B per thread per chunk (A:4, B:8) ----
    const int r0 = tid >> 3;             // 0..31
    const int c8 = tid & 7;              // 16B col within 128B row
    const uint32_t colp = (uint32_t)((c8 ^ (r0 & 7)) * 16);
    const uint32_t dstA = r0 * 128 + colp;
    const uint32_t dstB = A_B + r0 * 128 + colp;
    const uint32_t cBo = c8 * 16;

    int pKB = 0, pG = cta, issued = 0;
    const char* bA0 = (const char*)g_Ahf
        + ((size_t)(pG >> 5) * BM + r0) * ROWBYTES + cBo;
    const char* bB0 = (const char*)g_Bhf
        + ((size_t)(pG & 31) * BN + r0) * ROWBYTES + cBo;

#define ISSUE() do {                                                        \
        const uint32_t stb = sbase + (uint32_t)(issued & 1) * STAGE_B;      \
        _Pragma("unroll")                                                   \
        for (int i = 0; i < 4; ++i)                                         \
            cpa16(stb + dstA + i * 4096,                                    \
                  bA0 + (size_t)i * 32 * ROWBYTES + pKB);                   \
        _Pragma("unroll")                                                   \
        for (int i = 0; i < 8; ++i)                                         \
            cpa16(stb + dstB + i * 4096,                                    \
                  bB0 + (size_t)i * 32 * ROWBYTES + pKB);                   \
        asm volatile("cp.async.commit_group;" ::: "memory");                \
        ++issued;                                                           \
        pKB += 128;                                                         \
        if (pKB == DD * 2) {                                                \
            pKB = 0; pG += NCTA;                                            \
            if (pG < NTILES) {                                              \
                bA0 = (const char*)g_Ahf                                    \
                    + ((size_t)(pG >> 5) * BM + r0) * ROWBYTES + cBo;       \
                bB0 = (const char*)g_Bhf                                    \
                    + ((size_t)(pG & 31) * BN + r0) * ROWBYTES + cBo;       \
            }                                                               \
        }                                                                   \
    } while (0)

    // ---- ldmatrix per-lane addresses (SW128-style xor on 128B rows) ----
    const int rowA = warp_m * 64 + (lane & 15);
    const uint32_t ra7 = (uint32_t)(rowA & 7);
    const uint32_t ca = (uint32_t)(lane >> 4);
    uint32_t aAddr[4];
#pragma unroll
    for (int kk = 0; kk < 4; ++kk)
        aAddr[kk] = rowA * 128 + (((2u * kk + ca) ^ ra7) * 16);

    const int rowB = warp_n * 64 + (lane & 7) + ((lane >> 4) & 1) * 8;
    const uint32_t rb7 = (uint32_t)(lane & 7);
    const uint32_t cb = (uint32_t)((lane >> 3) & 1);
    uint32_t bAddr[4];
#pragma unroll
    for (int kk = 0; kk < 4; ++kk)
        bAddr[kk] = A_B + rowB * 128 + (((2u * kk + cb) ^ rb7) * 16);

    // ---- prologue: fill both stages, certify chunk 0 ----
    ISSUE(); ISSUE();
    asm volatile("cp.async.wait_group 1;" ::: "memory");
    __syncthreads();

    int ch = 0;
    int g = cta;
#pragma unroll 1
    for (int t = 0; t < ntiles; ++t, g += NCTA) {
        uint32_t acc[4][8][2];
#pragma unroll
        for (int mt = 0; mt < 4; ++mt)
#pragma unroll
            for (int nt = 0; nt < 8; ++nt) { acc[mt][nt][0] = 0u; acc[mt][nt][1] = 0u; }

#pragma unroll 1
        for (int it = 0; it < KITERS; ++it, ++ch) {
            const uint32_t sS = sbase + (uint32_t)(ch & 1) * STAGE_B;
            uint32_t a[4][4], b[4][4];

            // kk = 0..2: load + MMA
#pragma unroll
            for (int kk = 0; kk < 3; ++kk) {
#pragma unroll
                for (int mt = 0; mt < 4; ++mt)
                    ldm_x4(a[mt], sS + aAddr[kk] + mt * 2048);
#pragma unroll
                for (int np = 0; np < 4; ++np)
                    ldm_x4(b[np], sS + bAddr[kk] + np * 2048);
#pragma unroll
                for (int mt = 0; mt < 4; ++mt)
#pragma unroll
                    for (int nt = 0; nt < 8; ++nt)
                        mma16816h(acc[mt][nt], a[mt], &b[nt >> 1][(nt & 1) * 2]);
            }

            // kk = 3: load fragments (they survive the barrier in registers)
#pragma unroll
            for (int mt = 0; mt < 4; ++mt)
                ldm_x4(a[mt], sS + aAddr[3] + mt * 2048);
#pragma unroll
            for (int np = 0; np < 4; ++np)
                ldm_x4(b[np], sS + bAddr[3] + np * 2048);

            // certify chunk ch+1; quiesce readers of stage ch&1; refill it
            asm volatile("cp.async.wait_group 0;" ::: "memory");
            __syncthreads();
            if (issued < C) ISSUE();

            // kk = 3 MMA: pure tensor work flowing out of the barrier
#pragma unroll
            for (int mt = 0; mt < 4; ++mt)
#pragma unroll
                for (int nt = 0; nt < 8; ++nt)
                    mma16816h(acc[mt][nt], a[mt], &b[nt >> 1][(nt & 1) * 2]);
        }

        // ---- de-synchronized epilogue (no barriers) ----
        const float SCALE = 2.302585092994046f, BIAS = -10.0f;
        const __half2 S2  = __floats2half2_rn(SCALE, SCALE);
        const __half2 Bi2 = __floats2half2_rn(BIAS, BIAS);
        const __half2 NL2 = __floats2half2_rn(-1.4426950408889634f,
                                              -1.4426950408889634f);
        const __half2 ONE2 = __floats2half2_rn(1.0f, 1.0f);
        const __half2 ZERO2 = __floats2half2_rn(0.0f, 0.0f);
        float lsum = 0.0f;
#pragma unroll
        for (int mt = 0; mt < 4; ++mt) {
#pragma unroll
            for (int q = 0; q < 4; ++q) {      // group of 2 nt = 4 half2 = 8 elems
                __half2 zz[4];
#pragma unroll
                for (int h = 0; h < 2; ++h)
#pragma unroll
                    for (int v = 0; v < 2; ++v)
                        zz[h * 2 + v] = __hfma2(
                            *(const __half2*)&acc[mt][2 * q + h][v], S2, Bi2);
                // max(z,0) part
                __half2 s2 = __hadd2(
                    __hadd2(__hmax2(zz[0], ZERO2), __hmax2(zz[1], ZERO2)),
                    __hadd2(__hmax2(zz[2], ZERO2), __hmax2(zz[3], ZERO2)));
                float2 fs = __half22float2(s2);
                lsum += fs.x + fs.y;
                // log(1+exp(-|z|)) part via product of 8 factors (<=256)
                __half2 p2 = __hmul2(
                    __hmul2(__hadd2(sp_h2exp2(__hmul2(__habs2(zz[0]), NL2)), ONE2),
                            __hadd2(sp_h2exp2(__hmul2(__habs2(zz[1]), NL2)), ONE2)),
                    __hmul2(__hadd2(sp_h2exp2(__hmul2(__habs2(zz[2]), NL2)), ONE2),
                            __hadd2(sp_h2exp2(__hmul2(__habs2(zz[3]), NL2)), ONE2)));
                float2 fp = __half22float2(p2);
                lsum += __logf(fp.x * fp.y);
            }
        }
        // diagonal correction: softplus(-z) = softplus(z) - z  (exact identity)
        if ((g >> 6) == (g & 31)) {
            const int rowOff = ((g >> 5) & 1) * 128;   // tile-local col of row 0
#pragma unroll
            for (int mt = 0; mt < 4; ++mt) {
                const int row = rowOff + warp_m * 64 + mt * 16 + (lane >> 2);
#pragma unroll
                for (int nt = 0; nt < 8; ++nt) {
                    const int col0 = warp_n * 64 + nt * 8 + (lane & 3) * 2;
#pragma unroll
                    for (int v = 0; v < 2; ++v) {
                        const int r_ = row + v * 8;
                        if (r_ == col0 || r_ == col0 + 1) {
                            float2 f = __half22float2(
                                *(const __half2*)&acc[mt][nt][v]);
                            float zd = (r_ == col0) ? fmaf(f.x, SCALE, BIAS)
                                                    : fmaf(f.y, SCALE, BIAS);
                            lsum -= zd;
                        }
                    }
                }
            }
        }
#pragma unroll
        for (int off = 16; off > 0; off >>= 1)
            lsum += __shfl_down_sync(0xFFFFFFFFu, lsum, off);
        if (lane == 0) g_partials8[g * 8 + wid] = lsum;
    }
#undef ISSUE

    // ---- last CTA out performs the deterministic finalize ----
    __threadfence();
    __syncthreads();
    if (tid == 0)
        s_last = (atomicAdd(&g_done, 1u) == NCTA - 1) ? 1u : 0u;
    __syncthreads();
    if (s_last) {
        __threadfence();
        double* sd = (double*)smem_raw;    // stage buffers dead
        double s = 0.0;
        for (int i = tid; i < NTILES * 8; i += 256)
            s += (double)g_partials8[i];
        sd[tid] = s;
        __syncthreads();
#pragma unroll
        for (int off = 128; off > 0; off >>= 1) {
            if (tid < off) sd[tid] += sd[tid + off];
            __syncthreads();
        }
        if (tid == 0) out[0] = (float)(sd[0] / (double)NN);
    }
}

extern "C" void kernel_launch(void* const* d_in, const int* in_sizes, int n_in,
                              void* d_out, int out_size) {
    cudaFuncSetAttribute(siglip_mma_kernel,
                         cudaFuncAttributeMaxDynamicSharedMemorySize, SMEM_TOTAL);
    convert_kernel<<<2048, 256>>>((const float*)d_in[0], (const float*)d_in[1]);
    siglip_mma_kernel<<<NCTA, 256, SMEM_TOTAL>>>((float*)d_out);
}